// round 15
// baseline (speedup 1.0000x reference)
#include <cuda_runtime.h>

#define NB 4
#define NK 128
#define NG 128

// ---- output layout (float32, tuple flattenend & concatenated) ----
#define OFF_ROIS    0
#define OFF_OBJ     2048
#define OFF_DELTAS  526336
#define OFF_RANKS   528384
#define OFF_SPATIAL 528896

// grid = 256, block = 256. Block g owns sources sA=2g, sB=2g+1 of image
// b = sA>>7. FULLY FEED-FORWARD: no inter-block sync. Each block locally
// recomputes the image's 128 pos bits with the division-free test
//   iou >= 0.5  <=>  3*inter >= area_p + area_g
// (no argmax needed for pos), derives dest via popcount, and scatters.
__global__ void __launch_bounds__(256) fused_kernel(
    const float* __restrict__ proposals,
    const float* __restrict__ obj_feat,
    const float* __restrict__ gt_boxes,
    const int*   __restrict__ gt_ranks,
    float*       __restrict__ out)
{
    const int g    = blockIdx.x;
    const int sA   = g * 2;
    const int sB   = sA + 1;
    const int b    = sA >> 7;
    const int t    = threadIdx.x;
    const int side = t >> 7;          // 0 = proposal A, 1 = proposal B
    const int lt   = t & 127;

    // ---- payload loads first: 2 independent DRAM streams ----
    const float4 payA = ((const float4*)obj_feat)[(size_t)sA * 256 + t];
    const float4 payB = ((const float4*)obj_feat)[(size_t)sB * 256 + t];

    __shared__ float4 s_prop[NK];
    __shared__ float4 s_gt[NG];
    __shared__ float  s_bi[8], s_bu[8];
    __shared__ int    s_bj[8];
    __shared__ unsigned char s_pp[2][NK];   // partial pos per segment
    __shared__ unsigned s_mask[4];
    __shared__ int    s_dest[2];
    __shared__ int4   s_box[2];

    if (t < NK) s_prop[t]    = ((const float4*)proposals)[(b << 7) + t];
    else        s_gt[t - NK] = ((const float4*)gt_boxes)[(b << 7) + (t - NK)];
    __syncthreads();

    // ---- own-proposal argmax (verified round-13 layout):
    //      warps 0-3 -> A, warps 4-7 -> B; lane lt handles GT index lt ----
    {
        const float4 pr = s_prop[(side ? sB : sA) & 127];
        const float ap = (pr.z - pr.x) * (pr.w - pr.y);
        const float4 gt = s_gt[lt];
        const float dy = fminf(pr.z, gt.z) - fmaxf(pr.x, gt.x);
        const float dx = fminf(pr.w, gt.w) - fmaxf(pr.y, gt.y);
        float bi = fmaxf(dx, 0.0f) * fmaxf(dy, 0.0f);
        float bu = ap + (gt.z - gt.x) * (gt.w - gt.y) - bi;
        int   bj = lt;
        // shfl_down partner has HIGHER gt index; strict > keeps first max
        #pragma unroll
        for (int off = 16; off; off >>= 1) {
            const float oi = __shfl_down_sync(0xFFFFFFFFu, bi, off);
            const float ou = __shfl_down_sync(0xFFFFFFFFu, bu, off);
            const int   oj = __shfl_down_sync(0xFFFFFFFFu, bj, off);
            if (oi * bu > bi * ou) { bi = oi; bu = ou; bj = oj; }
        }
        if ((t & 31) == 0) { s_bi[t >> 5] = bi; s_bu[t >> 5] = bu; s_bj[t >> 5] = bj; }
    }

    // ---- all-pos recompute: thread handles proposal q = t&127 over the
    //      GT half [64*seg, 64*seg+64). Division-free, chain-free OR. ----
    {
        const int q   = t & 127;
        const int seg = t >> 7;
        const float4 pr = s_prop[q];
        const float ap = (pr.z - pr.x) * (pr.w - pr.y);
        int posp = 0;
        const int j0 = seg * 64;
        #pragma unroll 8
        for (int j = j0; j < j0 + 64; j++) {
            const float4 gt = s_gt[j];
            const float dy = fminf(pr.z, gt.z) - fmaxf(pr.x, gt.x);
            const float dx = fminf(pr.w, gt.w) - fmaxf(pr.y, gt.y);
            const float inter = fmaxf(dx, 0.0f) * fmaxf(dy, 0.0f);
            const float ag = (gt.z - gt.x) * (gt.w - gt.y);
            posp |= (3.0f * inter >= ap + ag) ? 1 : 0;
        }
        s_pp[seg][q] = (unsigned char)posp;
    }
    __syncthreads();

    // ---- combine halves + ballot (warps 0-3; whole-warp-uniform guard) ----
    if (t < NK) {
        const int posq = s_pp[0][t] | s_pp[1][t];
        const unsigned m = __ballot_sync(0xFFFFFFFFu, posq);
        if ((t & 31) == 0) s_mask[t >> 5] = m;
    }
    __syncthreads();

    // ---- leaders t=0 (A) and t=128 (B): finish own proposal ----
    if (lt == 0) {
        const int p  = (side ? sB : sA) & 127;
        const int w0 = side * 4;
        // merge this side's 4 warp winners in ascending order
        float bi = s_bi[w0], bu = s_bu[w0];
        int   bj = s_bj[w0];
        #pragma unroll
        for (int w = 1; w < 4; w++)
            if (s_bi[w0 + w] * bu > bi * s_bu[w0 + w]) {
                bi = s_bi[w0 + w]; bu = s_bu[w0 + w]; bj = s_bj[w0 + w];
            }

        const unsigned m0 = s_mask[0], m1 = s_mask[1], m2 = s_mask[2], m3 = s_mask[3];
        const int pos = (((p < 32 ? m0 : p < 64 ? m1 : p < 96 ? m2 : m3)
                          >> (p & 31)) & 1u);

        const float4 pr = s_prop[p];
        const float4 gb = s_gt[bj];
        float gy1 = gb.x, gx1 = gb.y, gy2 = gb.z, gx2 = gb.w;
        float4 dl = make_float4(0.f, 0.f, 0.f, 0.f);
        float rk = 0.0f;
        if (pos) {
            const float h  = pr.z - pr.x, wd = pr.w - pr.y;
            const float cy = pr.x + 0.5f * h, cx = pr.y + 0.5f * wd;
            const float gh = gy2 - gy1, gw = gx2 - gx1;
            const float gcy = gy1 + 0.5f * gh, gcx = gx1 + 0.5f * gw;
            dl.x = ((gcy - cy) / h)  / 0.1f;
            dl.y = ((gcx - cx) / wd) / 0.1f;
            dl.z = logf(gh / h)  / 0.2f;
            dl.w = logf(gw / wd) / 0.2f;
            rk = (float)gt_ranks[b * NG + bj];
        } else {
            gy1 = gx1 = gy2 = gx2 = 0.0f;    // roi_gt = 0 for negatives
        }

        // integer spatial box (window transform + denorm + round-half-even)
        int4 box;
        {
            const float win0 = 128.0f / 1023.0f;
            const float win2 = 895.0f / 1023.0f;
            const float wsc  = win2 - win0;
            int by1 = (int)rintf(((gy1 - win0) / wsc) * 479.0f);
            int bx1 = (int)rintf(gx1 * 639.0f);
            int by2 = (int)rintf(((gy2 - win0) / wsc) * 479.0f + 1.0f);
            int bx2 = (int)rintf(gx2 * 639.0f + 1.0f);
            if (!((by2 - by1) * (bx2 - bx1) > 0)) { by1 = bx1 = by2 = bx2 = 0; }
            box = make_int4(by1, bx1, by2, bx2);
        }

        // stable-partition destination from the mask words
        const int npos = __popc(m0) + __popc(m1) + __popc(m2) + __popc(m3);
        const int wq = p >> 5, lq = p & 31;
        const unsigned mw = (wq == 0) ? m0 : (wq == 1) ? m1 : (wq == 2) ? m2 : m3;
        const unsigned below_m = (lq == 0) ? 0u : (mw & ((1u << lq) - 1u));
        int below = __popc(below_m);
        if (wq > 0) below += __popc(m0);
        if (wq > 1) below += __popc(m1);
        if (wq > 2) below += __popc(m2);
        const int dest = pos ? below : (npos + (p - below));
        const int dbo  = (b << 7) + dest;

        ((float4*)(out + OFF_ROIS))[dbo]   = pr;
        ((float4*)(out + OFF_DELTAS))[dbo] = dl;
        out[OFF_RANKS + dbo] = rk;

        s_dest[side] = dest;
        s_box[side]  = box;
    }
    __syncthreads();

    // ---- scatter: both payloads + analytic spatial maps ----
    const int dboA = (b << 7) + s_dest[0];
    const int dboB = (b << 7) + s_dest[1];
    const int4 bxA = s_box[0];
    const int4 bxB = s_box[1];

    ((float4*)(out + OFF_OBJ))[(size_t)dboA * 256 + t] = payA;
    ((float4*)(out + OFF_OBJ))[(size_t)dboB * 256 + t] = payB;

    // analytic spatial: thread t writes float4 covering elements [4t, 4t+4)
    const int row  = t >> 3;
    const int col0 = (t & 7) * 4;
    float4 vA = make_float4(0.f, 0.f, 0.f, 0.f);
    float4 vB = make_float4(0.f, 0.f, 0.f, 0.f);
    if (row >= 4 && row < 28) {
        const int r1 = 20 * (row - 4) + 9;
        const float fyA = (float)((bxA.x < r1)     && (r1     < bxA.z))
                        + (float)((bxA.x < r1 + 1) && (r1 + 1 < bxA.z));
        const float fyB = (float)((bxB.x < r1)     && (r1     < bxB.z))
                        + (float)((bxB.x < r1 + 1) && (r1 + 1 < bxB.z));
        const float scA = 0.25f * fyA;
        const float scB = 0.25f * fyB;
        float* pA = &vA.x;
        float* pB = &vB.x;
        #pragma unroll
        for (int k = 0; k < 4; k++) {
            const int c1 = 20 * (col0 + k) + 9;
            const float fxA = (float)((bxA.y < c1)     && (c1     < bxA.w))
                            + (float)((bxA.y < c1 + 1) && (c1 + 1 < bxA.w));
            const float fxB = (float)((bxB.y < c1)     && (c1     < bxB.w))
                            + (float)((bxB.y < c1 + 1) && (c1 + 1 < bxB.w));
            pA[k] = scA * fxA;
            pB[k] = scB * fxB;
        }
    }
    ((float4*)(out + OFF_SPATIAL))[(size_t)dboA * 256 + t] = vA;
    ((float4*)(out + OFF_SPATIAL))[(size_t)dboB * 256 + t] = vB;
}

extern "C" void kernel_launch(void* const* d_in, const int* in_sizes, int n_in,
                              void* d_out, int out_size)
{
    const float* proposals = (const float*)d_in[0];
    const float* obj_feat  = (const float*)d_in[1];
    const float* gt_boxes  = (const float*)d_in[2];
    const int*   gt_ranks  = (const int*)  d_in[3];
    float* out = (float*)d_out;

    fused_kernel<<<256, 256>>>(proposals, obj_feat, gt_boxes, gt_ranks, out);
}

// round 16
// speedup vs baseline: 1.2255x; 1.2255x over previous
#include <cuda_runtime.h>

#define NB 4
#define NK 128
#define NG 128

// ---- output layout (float32, tuple flattened & concatenated) ----
#define OFF_ROIS    0
#define OFF_OBJ     2048
#define OFF_DELTAS  526336
#define OFF_RANKS   528384
#define OFF_SPATIAL 528896

// Per-image sync state, one 128B line each (zero-initialized; the 128th
// done-arriver of each image resets it for the next launch).
struct __align__(128) ImgSync {
    unsigned long long arrive[2];   // 128 arrival bits
    unsigned long long pos[2];      // 128 positive bits
    int done;
    int pad[23];
};
__device__ ImgSync g_sync[NB];

// grid = 256, block = 256. Block g owns sources sA=2g, sB=2g+1 of image
// b = sA>>7. Warps 0-3 -> A, warps 4-7 -> B; lane lt handles GT index lt.
// EARLY PUBLISH: pos is derived division-free per lane (3*inter >= ap+ag),
// combined by ballot + one barrier, and published BEFORE the argmax reduce;
// the argmax/deltas/box work overlaps the global wait.
__global__ void __launch_bounds__(256) fused_kernel(
    const float* __restrict__ proposals,
    const float* __restrict__ obj_feat,
    const float* __restrict__ gt_boxes,
    const int*   __restrict__ gt_ranks,
    float*       __restrict__ out)
{
    const int g    = blockIdx.x;
    const int sA   = g * 2;
    const int sB   = sA + 1;
    const int b    = sA >> 7;
    const int t    = threadIdx.x;
    const int side = t >> 7;          // 0 = proposal A, 1 = proposal B
    const int lt   = t & 127;
    const int w    = t >> 5;          // warp id 0..7

    // ---- payload loads first: 2 independent DRAM streams ----
    const float4 payA = ((const float4*)obj_feat)[(size_t)sA * 256 + t];
    const float4 payB = ((const float4*)obj_feat)[(size_t)sB * 256 + t];

    __shared__ unsigned s_pa[8];      // per-warp pos-test ballot (32 GTs each)
    __shared__ float s_bi[8], s_bu[8];
    __shared__ int   s_bj[8];
    __shared__ int   s_dest[2];
    __shared__ int4  s_box[2];

    // ---- per-lane IoU for own proposal, GT index lt ----
    const int s  = side ? sB : sA;
    const int p  = s & 127;
    const float4 pr = ((const float4*)proposals)[s];            // broadcast
    const float4 gt = ((const float4*)gt_boxes)[(b << 7) + lt];
    const float ap = (pr.z - pr.x) * (pr.w - pr.y);
    const float dy = fminf(pr.z, gt.z) - fmaxf(pr.x, gt.x);
    const float dx = fminf(pr.w, gt.w) - fmaxf(pr.y, gt.y);
    float bi = fmaxf(dx, 0.0f) * fmaxf(dy, 0.0f);               // inter
    const float ag = (gt.z - gt.x) * (gt.w - gt.y);
    float bu = ap + ag - bi;                                    // union
    int   bj = lt;

    // division-free pos test (validated round 15): iou>=0.5 <=> 3*inter>=ap+ag
    const unsigned m = __ballot_sync(0xFFFFFFFFu, 3.0f * bi >= ap + ag);
    if ((t & 31) == 0) s_pa[w] = m;
    __syncthreads();

    // ---- leaders publish IMMEDIATELY (argmax not needed for pos) ----
    int pos = 0;
    if (lt == 0) {
        const int w0 = side * 4;
        pos = ((s_pa[w0] | s_pa[w0 + 1] | s_pa[w0 + 2] | s_pa[w0 + 3]) != 0u);
        ImgSync* S = &g_sync[b];
        const unsigned long long bit = 1ULL << (p & 63);
        const int w64 = p >> 6;
        if (pos)
            asm volatile("red.relaxed.gpu.global.or.b64 [%0], %1;"
                         :: "l"(&S->pos[w64]), "l"(bit) : "memory");
        asm volatile("red.release.gpu.global.or.b64 [%0], %1;"
                     :: "l"(&S->arrive[w64]), "l"(bit) : "memory");
    }

    // ---- argmax reduce (overlaps other blocks' publishes) ----
    // shfl_down partner has HIGHER gt index; strict > keeps first max.
    #pragma unroll
    for (int off = 16; off; off >>= 1) {
        const float oi = __shfl_down_sync(0xFFFFFFFFu, bi, off);
        const float ou = __shfl_down_sync(0xFFFFFFFFu, bu, off);
        const int   oj = __shfl_down_sync(0xFFFFFFFFu, bj, off);
        if (oi * bu > bi * ou) { bi = oi; bu = ou; bj = oj; }
    }
    if ((t & 31) == 0) { s_bi[w] = bi; s_bu[w] = bu; s_bj[w] = bj; }
    __syncthreads();

    // ---- leaders: merge, precompute, wait, derive dest, write scalars ----
    if (lt == 0) {
        const int w0 = side * 4;
        float mbi = s_bi[w0], mbu = s_bu[w0];
        int   mbj = s_bj[w0];
        #pragma unroll
        for (int ww = 1; ww < 4; ww++)
            if (s_bi[w0 + ww] * mbu > mbi * s_bu[w0 + ww]) {
                mbi = s_bi[w0 + ww]; mbu = s_bu[w0 + ww]; mbj = s_bj[w0 + ww];
            }

        const float4 gb = ((const float4*)gt_boxes)[(b << 7) + mbj];
        float gy1 = gb.x, gx1 = gb.y, gy2 = gb.z, gx2 = gb.w;
        float4 dl = make_float4(0.f, 0.f, 0.f, 0.f);
        float rk = 0.0f;
        if (pos) {
            const float h  = pr.z - pr.x, wd = pr.w - pr.y;
            const float cy = pr.x + 0.5f * h, cx = pr.y + 0.5f * wd;
            const float gh = gy2 - gy1, gw = gx2 - gx1;
            const float gcy = gy1 + 0.5f * gh, gcx = gx1 + 0.5f * gw;
            dl.x = ((gcy - cy) / h)  / 0.1f;
            dl.y = ((gcx - cx) / wd) / 0.1f;
            dl.z = logf(gh / h)  / 0.2f;
            dl.w = logf(gw / wd) / 0.2f;
            rk = (float)gt_ranks[b * NG + mbj];
        } else {
            gy1 = gx1 = gy2 = gx2 = 0.0f;    // roi_gt = 0 for negatives
        }
        int4 box;
        {
            // integer spatial box (window transform + denorm + round-half-even)
            const float win0 = 128.0f / 1023.0f;
            const float win2 = 895.0f / 1023.0f;
            const float wsc  = win2 - win0;
            int by1 = (int)rintf(((gy1 - win0) / wsc) * 479.0f);
            int bx1 = (int)rintf(gx1 * 639.0f);
            int by2 = (int)rintf(((gy2 - win0) / wsc) * 479.0f + 1.0f);
            int bx2 = (int)rintf(gx2 * 639.0f + 1.0f);
            if (!((by2 - by1) * (bx2 - bx1) > 0)) { by1 = bx1 = by2 = bx2 = 0; }
            box = make_int4(by1, bx1, by2, bx2);
        }

        // ---- wait: relaxed polls, single acquire pass on completion ----
        ImgSync* S = &g_sync[b];
        unsigned long long a0, a1;
        int spins = 0;
        for (;;) {
            asm volatile("ld.relaxed.gpu.global.b64 %0, [%1];"
                         : "=l"(a0) : "l"(&S->arrive[0]) : "memory");
            asm volatile("ld.relaxed.gpu.global.b64 %0, [%1];"
                         : "=l"(a1) : "l"(&S->arrive[1]) : "memory");
            if ((a0 & a1) == ~0ULL) break;
            if (++spins > 128) __nanosleep(32);
        }
        // acquire fence-load orders the subsequent pos reads after all arrives
        asm volatile("ld.acquire.gpu.global.b64 %0, [%1];"
                     : "=l"(a0) : "l"(&S->arrive[0]) : "memory");
        unsigned long long p0, p1;
        asm volatile("ld.relaxed.gpu.global.b64 %0, [%1];"
                     : "=l"(p0) : "l"(&S->pos[0]) : "memory");
        asm volatile("ld.relaxed.gpu.global.b64 %0, [%1];"
                     : "=l"(p1) : "l"(&S->pos[1]) : "memory");

        const int npos = __popcll(p0) + __popcll(p1);
        const unsigned long long bit = 1ULL << (p & 63);
        const unsigned long long myw = (p < 64) ? p0 : p1;
        int below = __popcll(myw & (bit - 1));
        if (p >= 64) below += __popcll(p0);
        const int dest = pos ? below : (npos + (p - below));
        const int dbo  = (b << 7) + dest;

        // done counter; the 128th arriver resets this image's sync
        int old, one = 1;
        asm volatile("atom.release.gpu.global.add.s32 %0, [%1], %2;"
                     : "=r"(old) : "l"(&S->done), "r"(one) : "memory");
        if (old == NK - 1) {
            const unsigned long long z = 0ULL;
            asm volatile("st.relaxed.gpu.global.b64 [%0], %1;" :: "l"(&S->arrive[0]), "l"(z) : "memory");
            asm volatile("st.relaxed.gpu.global.b64 [%0], %1;" :: "l"(&S->arrive[1]), "l"(z) : "memory");
            asm volatile("st.relaxed.gpu.global.b64 [%0], %1;" :: "l"(&S->pos[0]),    "l"(z) : "memory");
            asm volatile("st.relaxed.gpu.global.b64 [%0], %1;" :: "l"(&S->pos[1]),    "l"(z) : "memory");
            int zi = 0;
            asm volatile("st.relaxed.gpu.global.b32 [%0], %1;" :: "l"(&S->done), "r"(zi) : "memory");
        }

        // scalar outputs for this ROI
        ((float4*)(out + OFF_ROIS))[dbo]   = pr;
        ((float4*)(out + OFF_DELTAS))[dbo] = dl;
        out[OFF_RANKS + dbo] = rk;

        s_dest[side] = dest;
        s_box[side]  = box;
    }
    __syncthreads();

    // ---- scatter: both payloads + analytic spatial maps ----
    const int dboA = (b << 7) + s_dest[0];
    const int dboB = (b << 7) + s_dest[1];
    const int4 bxA = s_box[0];
    const int4 bxB = s_box[1];

    ((float4*)(out + OFF_OBJ))[(size_t)dboA * 256 + t] = payA;
    ((float4*)(out + OFF_OBJ))[(size_t)dboB * 256 + t] = payB;

    // analytic spatial: thread t writes float4 covering elements [4t, 4t+4)
    const int row  = t >> 3;
    const int col0 = (t & 7) * 4;
    float4 vA = make_float4(0.f, 0.f, 0.f, 0.f);
    float4 vB = make_float4(0.f, 0.f, 0.f, 0.f);
    if (row >= 4 && row < 28) {
        const int r1 = 20 * (row - 4) + 9;
        const float fyA = (float)((bxA.x < r1)     && (r1     < bxA.z))
                        + (float)((bxA.x < r1 + 1) && (r1 + 1 < bxA.z));
        const float fyB = (float)((bxB.x < r1)     && (r1     < bxB.z))
                        + (float)((bxB.x < r1 + 1) && (r1 + 1 < bxB.z));
        const float scA = 0.25f * fyA;
        const float scB = 0.25f * fyB;
        float* pA = &vA.x;
        float* pB = &vB.x;
        #pragma unroll
        for (int k = 0; k < 4; k++) {
            const int c1 = 20 * (col0 + k) + 9;
            const float fxA = (float)((bxA.y < c1)     && (c1     < bxA.w))
                            + (float)((bxA.y < c1 + 1) && (c1 + 1 < bxA.w));
            const float fxB = (float)((bxB.y < c1)     && (c1     < bxB.w))
                            + (float)((bxB.y < c1 + 1) && (c1 + 1 < bxB.w));
            pA[k] = scA * fxA;
            pB[k] = scB * fxB;
        }
    }
    ((float4*)(out + OFF_SPATIAL))[(size_t)dboA * 256 + t] = vA;
    ((float4*)(out + OFF_SPATIAL))[(size_t)dboB * 256 + t] = vB;
}

extern "C" void kernel_launch(void* const* d_in, const int* in_sizes, int n_in,
                              void* d_out, int out_size)
{
    const float* proposals = (const float*)d_in[0];
    const float* obj_feat  = (const float*)d_in[1];
    const float* gt_boxes  = (const float*)d_in[2];
    const int*   gt_ranks  = (const int*)  d_in[3];
    float* out = (float*)d_out;

    fused_kernel<<<256, 256>>>(proposals, obj_feat, gt_boxes, gt_ranks, out);
}